// round 2
// baseline (speedup 1.0000x reference)
#include <cuda_runtime.h>
#include <cuda_bf16.h>
#include <cstddef>

// Problem constants
#define N_ 400000
#define E_ 1600000
#define B_ 8192
#define F_ 64
#define H_ 96

// ---------------- scratch (device globals; no allocations allowed) ----------------
__device__ float    g_bufA[(size_t)N_ * H_];   // 153.6 MB
__device__ float    g_bufB[(size_t)N_ * H_];   // 153.6 MB
__device__ float    g_dinv[N_];                // deg -> rsqrt(deg)
__device__ float    g_gate[N_];                // gate logits -> exp values
__device__ unsigned g_gmaxk[B_];               // monotone float keys for segment max
__device__ float    g_denom[B_];
__device__ float    g_att [2][B_ * F_];
__device__ float    g_mean[2][B_ * H_];
__device__ float    g_cnt [2][B_];

// monotone float <-> unsigned key (for atomicMax over floats incl. negatives)
__device__ __forceinline__ unsigned fkey(float f) {
    unsigned i = __float_as_uint(f);
    return (i & 0x80000000u) ? ~i : (i | 0x80000000u);
}
__device__ __forceinline__ float funkey(unsigned k) {
    return (k & 0x80000000u) ? __uint_as_float(k & 0x7fffffffu)
                             : __uint_as_float(~k);
}

// ---------------- pooling: init ----------------
__global__ void k_pool_init(int side) {
    int i = blockIdx.x * blockDim.x + threadIdx.x;
    if (i < B_ * H_) g_mean[side][i] = 0.f;
    if (i < B_ * F_) g_att[side][i] = 0.f;
    if (i < B_) { g_gmaxk[i] = 0u; g_denom[i] = 0.f; g_cnt[side][i] = 0.f; }
}

// ---------------- gate MLP: g = relu(x@W1+b1)@W2 + b2 ----------------
// 32 rows / block, 256 threads: thread = (row ty:0..31) x (unit-group tx:0..7, 8 units each)
__global__ void k_gate(const float* __restrict__ x, const float* __restrict__ W1,
                       const float* __restrict__ b1, const float* __restrict__ W2,
                       const float* __restrict__ b2) {
    __shared__ float xs[32][64];
    __shared__ float W1s[64][64];
    __shared__ float b1s[64], W2s[64];
    int tid = threadIdx.x;
    int row0 = blockIdx.x * 32;
    for (int i = tid; i < 512; i += 256) {          // 32*64/4
        int r = i >> 4, c = i & 15;
        *(float4*)&xs[r][c * 4] = *(const float4*)&x[(size_t)(row0 + r) * 64 + c * 4];
    }
    for (int i = tid; i < 1024; i += 256) {         // 64*64/4
        int r = i >> 4, c = i & 15;
        *(float4*)&W1s[r][c * 4] = *(const float4*)&W1[(size_t)r * 64 + c * 4];
    }
    if (tid < 64) { b1s[tid] = b1[tid]; W2s[tid] = W2[tid]; }
    __syncthreads();
    int ty = tid >> 3;   // row in tile
    int tx = tid & 7;    // unit group
    float acc[8];
#pragma unroll
    for (int u = 0; u < 8; ++u) acc[u] = b1s[tx * 8 + u];
    for (int k = 0; k < 64; ++k) {
        float xv = xs[ty][k];
#pragma unroll
        for (int u = 0; u < 8; ++u) acc[u] += xv * W1s[k][tx * 8 + u];
    }
    float s = 0.f;
#pragma unroll
    for (int u = 0; u < 8; ++u) s += fmaxf(acc[u], 0.f) * W2s[tx * 8 + u];
#pragma unroll
    for (int o = 4; o > 0; o >>= 1) s += __shfl_down_sync(0xffffffffu, s, o, 8);
    if (tx == 0) g_gate[row0 + ty] = s + b2[0];
}

// ---------------- segment max / expsum / weighted sum ----------------
__global__ void k_gmax(const int* __restrict__ batch) {
    int i = blockIdx.x * blockDim.x + threadIdx.x;
    if (i >= N_) return;
    atomicMax(&g_gmaxk[batch[i]], fkey(g_gate[i]));
}

__global__ void k_expsum(const int* __restrict__ batch, int side) {
    int i = blockIdx.x * blockDim.x + threadIdx.x;
    if (i >= N_) return;
    int b = batch[i];
    float e = expf(g_gate[i] - funkey(g_gmaxk[b]));
    g_gate[i] = e;
    atomicAdd(&g_denom[b], e);
    atomicAdd(&g_cnt[side][b], 1.f);   // node counts for mean pool (same batch array)
}

__global__ void k_attsum(const float* __restrict__ x, const int* __restrict__ batch, int side) {
    int gid = blockIdx.x * blockDim.x + threadIdx.x;   // N_*16
    if (gid >= N_ * 16) return;
    int i = gid / 16, c = gid % 16;
    int b = batch[i];
    float a = g_gate[i] / g_denom[b];
    float4 v = ((const float4*)x)[(size_t)i * 16 + c];
    v.x *= a; v.y *= a; v.z *= a; v.w *= a;
    atomicAdd(((float4*)g_att[side]) + (size_t)b * 16 + c, v);
}

// ---------------- degrees ----------------
__global__ void k_deg_init() {
    int i = blockIdx.x * blockDim.x + threadIdx.x;
    if (i < N_) g_dinv[i] = 1.f;   // self loop
}
__global__ void k_deg_edge(const int* __restrict__ dst) {
    int e = blockIdx.x * blockDim.x + threadIdx.x;
    if (e < E_) atomicAdd(&g_dinv[dst[e]], 1.f);
}
__global__ void k_rsqrt() {
    int i = blockIdx.x * blockDim.x + threadIdx.x;
    if (i < N_) g_dinv[i] = rsqrtf(g_dinv[i]);
}

// ---------------- aggregation: out = D^-1/2 (A+I) D^-1/2 in  (dim = DIMV*4) ----------------
template <int DIMV>
__global__ void k_self(const float* __restrict__ in, float* __restrict__ out) {
    int gid = blockIdx.x * blockDim.x + threadIdx.x;
    if (gid >= N_ * DIMV) return;
    int i = gid / DIMV;
    float d = g_dinv[i];
    float s = d * d;
    float4 v = ((const float4*)in)[gid];
    v.x *= s; v.y *= s; v.z *= s; v.w *= s;
    ((float4*)out)[gid] = v;   // also initializes out
}

template <int DIMV>
__global__ void k_edge(const float* __restrict__ in, float* __restrict__ out,
                       const int* __restrict__ src, const int* __restrict__ dst) {
    int gid = blockIdx.x * blockDim.x + threadIdx.x;
    if (gid >= E_ * DIMV) return;
    int e = gid / DIMV, c = gid % DIMV;
    int s = src[e], d = dst[e];
    float nrm = g_dinv[s] * g_dinv[d];
    float4 v = ((const float4*)in)[(size_t)s * DIMV + c];
    v.x *= nrm; v.y *= nrm; v.z *= nrm; v.w *= nrm;
    atomicAdd(((float4*)out) + (size_t)d * DIMV + c, v);
}

// ---------------- GEMM: C[N x 96] = A[N x FIN] @ W[FIN x 96] + b (opt relu) ----------------
// BM=64 rows/block, 256 threads, 4x6 micro-tile, KT=32 k-tiles.
template <int FIN, bool RELU>
__global__ void k_gemm(const float* __restrict__ A, const float* __restrict__ W,
                       const float* __restrict__ bias, float* __restrict__ C) {
    constexpr int KT = 32;
    __shared__ float Asm[64][KT];
    __shared__ float Wsm[KT][96];
    __shared__ float bsm[96];
    int tid = threadIdx.x;
    int row0 = blockIdx.x * 64;
    if (tid < 96) bsm[tid] = bias[tid];
    int tx = tid & 15, ty = tid >> 4;
    float acc[4][6];
#pragma unroll
    for (int r = 0; r < 4; ++r)
#pragma unroll
        for (int c = 0; c < 6; ++c) acc[r][c] = 0.f;

    for (int k0 = 0; k0 < FIN; k0 += KT) {
        __syncthreads();
        for (int i = tid; i < 64 * KT / 4; i += 256) {     // 512 float4
            int r = i >> 3, c = i & 7;
            *(float4*)&Asm[r][c * 4] =
                *(const float4*)&A[(size_t)(row0 + r) * FIN + k0 + c * 4];
        }
        for (int i = tid; i < KT * 96 / 4; i += 256) {     // 768 float4
            int r = i / 24, c = i % 24;
            *(float4*)&Wsm[r][c * 4] =
                *(const float4*)&W[(size_t)(k0 + r) * 96 + c * 4];
        }
        __syncthreads();
#pragma unroll
        for (int k = 0; k < KT; ++k) {
            float a[4];
#pragma unroll
            for (int r = 0; r < 4; ++r) a[r] = Asm[ty * 4 + r][k];
#pragma unroll
            for (int c = 0; c < 6; ++c) {
                float w = Wsm[k][tx * 6 + c];
#pragma unroll
                for (int r = 0; r < 4; ++r) acc[r][c] += a[r] * w;
            }
        }
    }
#pragma unroll
    for (int r = 0; r < 4; ++r) {
        int row = row0 + ty * 4 + r;
#pragma unroll
        for (int c = 0; c < 6; ++c) {
            int col = tx * 6 + c;
            float v = acc[r][c] + bsm[col];
            if (RELU) v = fmaxf(v, 0.f);
            C[(size_t)row * 96 + col] = v;
        }
    }
}

// ---------------- mean-pool accumulate ----------------
__global__ void k_meansum(const float* __restrict__ in, const int* __restrict__ batch, int side) {
    int gid = blockIdx.x * blockDim.x + threadIdx.x;    // N_*24
    if (gid >= N_ * 24) return;
    int i = gid / 24, c = gid % 24;
    atomicAdd(((float4*)g_mean[side]) + (size_t)batch[i] * 24 + c, ((const float4*)in)[gid]);
}

// ---------------- final MLP: one block per batch row ----------------
__global__ void k_final(const float* __restrict__ W0, const float* __restrict__ b0,
                        const float* __restrict__ W1, const float* __restrict__ b1,
                        float* __restrict__ out) {
    __shared__ float in[320];
    __shared__ float red[128];
    int b = blockIdx.x, t = threadIdx.x;   // 128 threads
    float icp = 1.f / fmaxf(g_cnt[0][b], 1.f);
    float icd = 1.f / fmaxf(g_cnt[1][b], 1.f);
    for (int i = t; i < 96; i += 128) {
        in[i]      = g_mean[0][(size_t)b * 96 + i] * icp;
        in[96 + i] = g_mean[1][(size_t)b * 96 + i] * icd;
    }
    for (int i = t; i < 64; i += 128) {
        in[192 + i] = g_att[0][(size_t)b * 64 + i];
        in[256 + i] = g_att[1][(size_t)b * 64 + i];
    }
    __syncthreads();
    float p = 0.f;
    if (t < 96) {
        float acc = b0[t];
        for (int k = 0; k < 320; ++k) acc += in[k] * W0[(size_t)k * 96 + t];
        p = fmaxf(acc, 0.f) * W1[t];
    }
    red[t] = p;
    __syncthreads();
    for (int s = 64; s > 0; s >>= 1) {
        if (t < s) red[t] += red[t + s];
        __syncthreads();
    }
    if (t == 0) out[b] = red[0] + b1[0];
}

// ---------------- launch ----------------
static inline int TB(int n) { return (n + 255) / 256; }

extern "C" void kernel_launch(void* const* d_in, const int* in_sizes, int n_in,
                              void* d_out, int out_size) {
    const float* x_p   = (const float*)d_in[0];
    const float* x_d   = (const float*)d_in[1];
    // d_in[2], d_in[3]: edge_attr — unused by the model
    const int*   ei_p  = (const int*)d_in[4];
    const int*   ei_d  = (const int*)d_in[5];
    const int*   bat_p = (const int*)d_in[6];
    const int*   bat_d = (const int*)d_in[7];
    const float* gW1 = (const float*)d_in[8];
    const float* gb1 = (const float*)d_in[9];
    const float* gW2 = (const float*)d_in[10];
    const float* gb2 = (const float*)d_in[11];
    const float* convW[2][3] = {
        {(const float*)d_in[12], (const float*)d_in[14], (const float*)d_in[16]},
        {(const float*)d_in[18], (const float*)d_in[20], (const float*)d_in[22]}};
    const float* convB[2][3] = {
        {(const float*)d_in[13], (const float*)d_in[15], (const float*)d_in[17]},
        {(const float*)d_in[19], (const float*)d_in[21], (const float*)d_in[23]}};
    const float* lW0 = (const float*)d_in[24];
    const float* lb0 = (const float*)d_in[25];
    const float* lW1 = (const float*)d_in[26];
    const float* lb1 = (const float*)d_in[27];
    float* out = (float*)d_out;

    float *bufA, *bufB;
    cudaGetSymbolAddress((void**)&bufA, g_bufA);
    cudaGetSymbolAddress((void**)&bufB, g_bufB);

    // ---- attention pools (use raw x) ----
    for (int side = 0; side < 2; ++side) {
        const float* x   = side ? x_d : x_p;
        const int*   bat = side ? bat_d : bat_p;
        k_pool_init<<<TB(B_ * H_), 256>>>(side);
        k_gate<<<N_ / 32, 256>>>(x, gW1, gb1, gW2, gb2);
        k_gmax<<<TB(N_), 256>>>(bat);
        k_expsum<<<TB(N_), 256>>>(bat, side);
        k_attsum<<<TB(N_ * 16), 256>>>(x, bat, side);
    }

    // ---- GCN stacks (aggregate-then-transform: agg(x)W == agg(xW)) ----
    for (int side = 0; side < 2; ++side) {
        const float* x   = side ? x_d : x_p;
        const int*   ei  = side ? ei_d : ei_p;
        const int*   bat = side ? bat_d : bat_p;
        const int* src = ei;
        const int* dst = ei + E_;

        k_deg_init<<<TB(N_), 256>>>();
        k_deg_edge<<<TB(E_), 256>>>(dst);
        k_rsqrt<<<TB(N_), 256>>>();

        // layer 1: agg over 64-dim input, then 64->96 GEMM + relu
        k_self<16><<<TB(N_ * 16), 256>>>(x, bufA);
        k_edge<16><<<TB(E_ * 16), 256>>>(x, bufA, src, dst);
        k_gemm<64, true><<<N_ / 64, 256>>>(bufA, convW[side][0], convB[side][0], bufB);

        // layer 2
        k_self<24><<<TB(N_ * 24), 256>>>(bufB, bufA);
        k_edge<24><<<TB(E_ * 24), 256>>>(bufB, bufA, src, dst);
        k_gemm<96, true><<<N_ / 64, 256>>>(bufA, convW[side][1], convB[side][1], bufB);

        // layer 3 (no relu)
        k_self<24><<<TB(N_ * 24), 256>>>(bufB, bufA);
        k_edge<24><<<TB(E_ * 24), 256>>>(bufB, bufA, src, dst);
        k_gemm<96, false><<<N_ / 64, 256>>>(bufA, convW[side][2], convB[side][2], bufB);

        k_meansum<<<TB(N_ * 24), 256>>>(bufB, bat, side);
    }

    // ---- final MLP ----
    k_final<<<B_, 128>>>(lW0, lb0, lW1, lb1, out);
}

// round 3
// speedup vs baseline: 1.0380x; 1.0380x over previous
#include <cuda_runtime.h>
#include <cstddef>

// Problem constants
#define N_ 400000
#define E_ 1600000
#define B_ 8192
#define F_ 64
#define H_ 96
#define NTILES_ ((N_ + 1023) / 1024)   // 391

// ---------------- scratch (device globals; no allocations allowed) ----------------
__device__ float    g_bufA[(size_t)N_ * H_];
__device__ float    g_bufB[(size_t)N_ * H_];
__device__ float    g_dinv[N_];
__device__ int      g_deg[N_];
__device__ int      g_rowptr[N_ + 1];
__device__ int      g_fill[N_];
__device__ int      g_csr[E_];
__device__ int      g_bsum[NTILES_];
__device__ float    g_gate[N_];
__device__ unsigned g_gmaxk[B_];
__device__ float    g_denom[B_];
__device__ float    g_att [2][B_ * F_];
__device__ float    g_mean[2][B_ * H_];
__device__ float    g_cntf[2][B_];

// packed fp32x2 FMA (Blackwell FFMA2 — only reachable via PTX)
__device__ __forceinline__ float2 ffma2(float2 a, float2 b, float2 c) {
    unsigned long long A = *reinterpret_cast<unsigned long long*>(&a);
    unsigned long long Bv = *reinterpret_cast<unsigned long long*>(&b);
    unsigned long long C = *reinterpret_cast<unsigned long long*>(&c);
    unsigned long long D;
    asm("fma.rn.f32x2 %0, %1, %2, %3;" : "=l"(D) : "l"(A), "l"(Bv), "l"(C));
    return *reinterpret_cast<float2*>(&D);
}

// monotone float <-> unsigned key (atomicMax over floats)
__device__ __forceinline__ unsigned fkey(float f) {
    unsigned i = __float_as_uint(f);
    return (i & 0x80000000u) ? ~i : (i | 0x80000000u);
}
__device__ __forceinline__ float funkey(unsigned k) {
    return (k & 0x80000000u) ? __uint_as_float(k & 0x7fffffffu)
                             : __uint_as_float(~k);
}

// ---------------- pooling init ----------------
__global__ void k_pool_init(int side) {
    int i = blockIdx.x * blockDim.x + threadIdx.x;
    if (i < B_ * H_) g_mean[side][i] = 0.f;
    if (i < B_ * F_) g_att[side][i] = 0.f;
    if (i < B_) { g_gmaxk[i] = 0u; g_denom[i] = 0.f; g_cntf[side][i] = 0.f; }
}

// ---------------- gate MLP: g = relu(x@W1+b1)@W2 + b2 (f32x2 GEMM) ----------------
// block = 64 rows, 256 threads. dyn smem: xT[64][68] | W1d float2[64][64] | b1s[64] | W2s[64]
__global__ void k_gate(const float* __restrict__ x, const float* __restrict__ W1,
                       const float* __restrict__ b1, const float* __restrict__ W2,
                       const float* __restrict__ b2) {
    extern __shared__ char sm_raw[];
    float*  xT  = (float*)sm_raw;
    float2* W1d = (float2*)(sm_raw + 64 * 68 * 4);
    float*  b1s = (float*)(sm_raw + 64 * 68 * 4 + 64 * 64 * 8);
    float*  W2s = b1s + 64;
    int tid = threadIdx.x;
    int row0 = blockIdx.x * 64;

    for (int i = tid; i < 64 * 64; i += 256) {
        float w = W1[i];
        W1d[i] = make_float2(w, w);
    }
    if (tid < 64) { b1s[tid] = b1[tid]; W2s[tid] = W2[tid]; }
    {
        int g = tid >> 2, l = tid & 3;
        const float4* sp = (const float4*)(x + (size_t)(row0 + g) * 64) + l * 4;
#pragma unroll
        for (int j = 0; j < 4; ++j) {
            float4 v = sp[j];
            int k = l * 16 + j * 4;
            xT[(k + 0) * 68 + g] = v.x;
            xT[(k + 1) * 68 + g] = v.y;
            xT[(k + 2) * 68 + g] = v.z;
            xT[(k + 3) * 68 + g] = v.w;
        }
    }
    __syncthreads();

    int cg = tid & 15, rg = tid >> 4;     // cg within warp -> shfl reduce
    int r0 = rg * 4, u0 = cg * 4;
    float2 acc2[2][4];
#pragma unroll
    for (int p = 0; p < 2; ++p)
#pragma unroll
        for (int c = 0; c < 4; ++c) acc2[p][c] = make_float2(0.f, 0.f);
#pragma unroll 4
    for (int k = 0; k < 64; ++k) {
        float2 a0 = *(const float2*)&xT[k * 68 + r0];
        float2 a1 = *(const float2*)&xT[k * 68 + r0 + 2];
#pragma unroll
        for (int c = 0; c < 4; ++c) {
            float2 w = W1d[k * 64 + u0 + c];
            acc2[0][c] = ffma2(a0, w, acc2[0][c]);
            acc2[1][c] = ffma2(a1, w, acc2[1][c]);
        }
    }
    float sr[4];
#pragma unroll
    for (int p = 0; p < 2; ++p) {
        float sx = 0.f, sy = 0.f;
#pragma unroll
        for (int c = 0; c < 4; ++c) {
            float bb = b1s[u0 + c], w2 = W2s[u0 + c];
            sx += fmaxf(acc2[p][c].x + bb, 0.f) * w2;
            sy += fmaxf(acc2[p][c].y + bb, 0.f) * w2;
        }
        sr[2 * p] = sx; sr[2 * p + 1] = sy;
    }
#pragma unroll
    for (int o = 8; o > 0; o >>= 1)
#pragma unroll
        for (int i = 0; i < 4; ++i)
            sr[i] += __shfl_xor_sync(0xffffffffu, sr[i], o, 16);
    if (cg == 0) {
        float bb = b2[0];
#pragma unroll
        for (int i = 0; i < 4; ++i) g_gate[row0 + r0 + i] = sr[i] + bb;
    }
}

// ---------------- segment max / expsum / weighted sum ----------------
__global__ void k_gmax(const int* __restrict__ batch) {
    int i = blockIdx.x * blockDim.x + threadIdx.x;
    if (i >= N_) return;
    atomicMax(&g_gmaxk[batch[i]], fkey(g_gate[i]));
}

__global__ void k_expsum(const int* __restrict__ batch, int side) {
    int i = blockIdx.x * blockDim.x + threadIdx.x;
    if (i >= N_) return;
    int b = batch[i];
    float e = expf(g_gate[i] - funkey(g_gmaxk[b]));
    g_gate[i] = e;
    atomicAdd(&g_denom[b], e);
    atomicAdd(&g_cntf[side][b], 1.f);
}

__global__ void k_attsum(const float* __restrict__ x, const int* __restrict__ batch, int side) {
    int gid = blockIdx.x * blockDim.x + threadIdx.x;   // N_*16
    if (gid >= N_ * 16) return;
    int i = gid / 16, c = gid % 16;
    int b = batch[i];
    float a = g_gate[i] / g_denom[b];
    float4 v = ((const float4*)x)[(size_t)i * 16 + c];
    v.x *= a; v.y *= a; v.z *= a; v.w *= a;
    atomicAdd(((float4*)g_att[side]) + (size_t)b * 16 + c, v);
}

// ---------------- CSR build (counting sort by dst) ----------------
__global__ void k_csr_init() {
    int i = blockIdx.x * blockDim.x + threadIdx.x;
    if (i < N_) { g_deg[i] = 0; g_fill[i] = 0; }
}
__global__ void k_count(const int* __restrict__ dst) {
    int e = blockIdx.x * blockDim.x + threadIdx.x;
    if (e < E_) atomicAdd(&g_deg[dst[e]], 1);
}
__global__ void k_scan1() {
    __shared__ int s[1024];
    int tx = threadIdx.x;
    int i = blockIdx.x * 1024 + tx;
    int v = (i < N_) ? g_deg[i] : 0;
    s[tx] = v;
    __syncthreads();
    for (int o = 1; o < 1024; o <<= 1) {
        int t = (tx >= o) ? s[tx - o] : 0;
        __syncthreads();
        s[tx] += t;
        __syncthreads();
    }
    if (i < N_) g_rowptr[i] = s[tx] - v;       // exclusive within tile
    if (tx == 1023) g_bsum[blockIdx.x] = s[1023];
}
__global__ void k_scan2() {
    __shared__ int s[512];
    int tx = threadIdx.x;
    int v = (tx < NTILES_) ? g_bsum[tx] : 0;
    s[tx] = v;
    __syncthreads();
    for (int o = 1; o < 512; o <<= 1) {
        int t = (tx >= o) ? s[tx - o] : 0;
        __syncthreads();
        s[tx] += t;
        __syncthreads();
    }
    if (tx < NTILES_) g_bsum[tx] = s[tx] - v;  // exclusive block offsets
}
__global__ void k_scan3() {
    int i = blockIdx.x * blockDim.x + threadIdx.x;
    if (i < N_) g_rowptr[i] += g_bsum[i >> 10];
    if (i == 0) g_rowptr[N_] = E_;
}
__global__ void k_fill(const int* __restrict__ src, const int* __restrict__ dst) {
    int e = blockIdx.x * blockDim.x + threadIdx.x;
    if (e >= E_) return;
    int d = dst[e];
    int pos = g_rowptr[d] + atomicAdd(&g_fill[d], 1);
    g_csr[pos] = src[e];
}
__global__ void k_dinv() {
    int i = blockIdx.x * blockDim.x + threadIdx.x;
    if (i < N_) g_dinv[i] = rsqrtf((float)(g_deg[i] + 1));
}

// ---------------- fused layer: out = relu?(agg(in) @ W + b), optional mean-pool ----------------
// block = 64 dst rows, 256 threads.
// dyn smem: As[FIN][68] (transposed agg) | Wd float2[FIN][96] (dup pairs) | bs[96]
// POOL < 0 : write out[row*96+col]; POOL >= 0 : atomicAdd into g_mean[POOL] (layer 3)
template <int FIN, bool RELU, int POOL>
__global__ void k_layer(const float* __restrict__ in, const float* __restrict__ W,
                        const float* __restrict__ bias, float* __restrict__ out,
                        const int* __restrict__ batch) {
    constexpr int VT = FIN / 16;    // float4 per gather thread (4 threads/node)
    extern __shared__ char sm_raw[];
    float*  As = (float*)sm_raw;
    float2* Wd = (float2*)(sm_raw + FIN * 68 * 4);
    float*  bs = (float*)(sm_raw + FIN * 68 * 4 + FIN * 96 * 8);
    int tid = threadIdx.x;
    int row0 = blockIdx.x * 64;

    for (int i = tid; i < FIN * 96; i += 256) {
        float w = W[i];
        Wd[i] = make_float2(w, w);
    }
    if (tid < 96) bs[tid] = bias[tid];

    // ---- gather phase: agg = dinv_d^2 * x_d + sum_nbr dinv_s*dinv_d * x_s ----
    {
        int g = tid >> 2, l = tid & 3;
        int node = row0 + g;
        float dn = g_dinv[node];
        float sc = dn * dn;
        float4 acc[VT];
        const float4* sp = (const float4*)(in + (size_t)node * FIN) + l * VT;
#pragma unroll
        for (int j = 0; j < VT; ++j) {
            float4 v = sp[j];
            acc[j] = make_float4(v.x * sc, v.y * sc, v.z * sc, v.w * sc);
        }
        int p1 = g_rowptr[node + 1];
        for (int p = g_rowptr[node]; p < p1; ++p) {
            int s = g_csr[p];
            float nrm = g_dinv[s] * dn;
            const float4* np = (const float4*)(in + (size_t)s * FIN) + l * VT;
#pragma unroll
            for (int j = 0; j < VT; ++j) {
                float4 v = np[j];
                acc[j].x += v.x * nrm; acc[j].y += v.y * nrm;
                acc[j].z += v.z * nrm; acc[j].w += v.w * nrm;
            }
        }
#pragma unroll
        for (int j = 0; j < VT; ++j) {
            int k = l * (VT * 4) + j * 4;
            As[(k + 0) * 68 + g] = acc[j].x;
            As[(k + 1) * 68 + g] = acc[j].y;
            As[(k + 2) * 68 + g] = acc[j].z;
            As[(k + 3) * 68 + g] = acc[j].w;
        }
    }
    __syncthreads();

    // ---- GEMM phase: [64 x FIN] @ [FIN x 96], thread tile 4 rows x 6 cols via f32x2 ----
    int rg = tid & 15, cg = tid >> 4;
    int r0 = rg * 4, c0 = cg * 6;
    float2 acc2[2][6];
#pragma unroll
    for (int p = 0; p < 2; ++p)
#pragma unroll
        for (int c = 0; c < 6; ++c) acc2[p][c] = make_float2(0.f, 0.f);
#pragma unroll 4
    for (int k = 0; k < FIN; ++k) {
        float2 a0 = *(const float2*)&As[k * 68 + r0];
        float2 a1 = *(const float2*)&As[k * 68 + r0 + 2];
#pragma unroll
        for (int c = 0; c < 6; ++c) {
            float2 w = Wd[k * 96 + c0 + c];
            acc2[0][c] = ffma2(a0, w, acc2[0][c]);
            acc2[1][c] = ffma2(a1, w, acc2[1][c]);
        }
    }

    // ---- epilogue ----
#pragma unroll
    for (int p = 0; p < 2; ++p) {
        int rA = row0 + r0 + 2 * p;
        int bA = 0, bB = 0;
        if (POOL >= 0) { bA = batch[rA]; bB = batch[rA + 1]; }
#pragma unroll
        for (int c = 0; c < 6; ++c) {
            int col = c0 + c;
            float vx = acc2[p][c].x + bs[col];
            float vy = acc2[p][c].y + bs[col];
            if (RELU) { vx = fmaxf(vx, 0.f); vy = fmaxf(vy, 0.f); }
            if (POOL < 0) {
                out[(size_t)rA * 96 + col] = vx;
                out[(size_t)(rA + 1) * 96 + col] = vy;
            } else {
                atomicAdd(&g_mean[POOL][(size_t)bA * 96 + col], vx);
                atomicAdd(&g_mean[POOL][(size_t)bB * 96 + col], vy);
            }
        }
    }
}

// ---------------- final MLP: one block per batch row ----------------
__global__ void k_final(const float* __restrict__ W0, const float* __restrict__ b0,
                        const float* __restrict__ W1, const float* __restrict__ b1,
                        float* __restrict__ out) {
    __shared__ float in[320];
    __shared__ float red[128];
    int b = blockIdx.x, t = threadIdx.x;   // 128 threads
    float icp = 1.f / fmaxf(g_cntf[0][b], 1.f);
    float icd = 1.f / fmaxf(g_cntf[1][b], 1.f);
    for (int i = t; i < 96; i += 128) {
        in[i]      = g_mean[0][(size_t)b * 96 + i] * icp;
        in[96 + i] = g_mean[1][(size_t)b * 96 + i] * icd;
    }
    for (int i = t; i < 64; i += 128) {
        in[192 + i] = g_att[0][(size_t)b * 64 + i];
        in[256 + i] = g_att[1][(size_t)b * 64 + i];
    }
    __syncthreads();
    float p = 0.f;
    if (t < 96) {
        float acc = b0[t];
        for (int k = 0; k < 320; ++k) acc += in[k] * W0[(size_t)k * 96 + t];
        p = fmaxf(acc, 0.f) * W1[t];
    }
    red[t] = p;
    __syncthreads();
    for (int s = 64; s > 0; s >>= 1) {
        if (t < s) red[t] += red[t + s];
        __syncthreads();
    }
    if (t == 0) out[b] = red[0] + b1[0];
}

// ---------------- launch ----------------
static inline int TB(int n) { return (n + 255) / 256; }

extern "C" void kernel_launch(void* const* d_in, const int* in_sizes, int n_in,
                              void* d_out, int out_size) {
    const float* x_p   = (const float*)d_in[0];
    const float* x_d   = (const float*)d_in[1];
    // d_in[2], d_in[3]: edge_attr — unused
    const int*   ei_p  = (const int*)d_in[4];
    const int*   ei_d  = (const int*)d_in[5];
    const int*   bat_p = (const int*)d_in[6];
    const int*   bat_d = (const int*)d_in[7];
    const float* gW1 = (const float*)d_in[8];
    const float* gb1 = (const float*)d_in[9];
    const float* gW2 = (const float*)d_in[10];
    const float* gb2 = (const float*)d_in[11];
    const float* convW[2][3] = {
        {(const float*)d_in[12], (const float*)d_in[14], (const float*)d_in[16]},
        {(const float*)d_in[18], (const float*)d_in[20], (const float*)d_in[22]}};
    const float* convB[2][3] = {
        {(const float*)d_in[13], (const float*)d_in[15], (const float*)d_in[17]},
        {(const float*)d_in[19], (const float*)d_in[21], (const float*)d_in[23]}};
    const float* lW0 = (const float*)d_in[24];
    const float* lb0 = (const float*)d_in[25];
    const float* lW1 = (const float*)d_in[26];
    const float* lb1 = (const float*)d_in[27];
    float* out = (float*)d_out;

    float *bufA, *bufB;
    cudaGetSymbolAddress((void**)&bufA, g_bufA);
    cudaGetSymbolAddress((void**)&bufB, g_bufB);

    const int SM_L64  = 64 * 68 * 4 + 64 * 96 * 8 + 96 * 4;    // 66944
    const int SM_L96  = 96 * 68 * 4 + 96 * 96 * 8 + 96 * 4;    // 100224
    const int SM_GATE = 64 * 68 * 4 + 64 * 64 * 8 + 2 * 64 * 4; // 50688
    cudaFuncSetAttribute(k_layer<64, true, -1>, cudaFuncAttributeMaxDynamicSharedMemorySize, SM_L64);
    cudaFuncSetAttribute(k_layer<96, true, -1>, cudaFuncAttributeMaxDynamicSharedMemorySize, SM_L96);
    cudaFuncSetAttribute(k_layer<96, false, 0>, cudaFuncAttributeMaxDynamicSharedMemorySize, SM_L96);
    cudaFuncSetAttribute(k_layer<96, false, 1>, cudaFuncAttributeMaxDynamicSharedMemorySize, SM_L96);
    cudaFuncSetAttribute(k_gate, cudaFuncAttributeMaxDynamicSharedMemorySize, SM_GATE);

    // ---- attention pools (raw x) ----
    for (int side = 0; side < 2; ++side) {
        const float* x   = side ? x_d : x_p;
        const int*   bat = side ? bat_d : bat_p;
        k_pool_init<<<TB(B_ * H_), 256>>>(side);
        k_gate<<<N_ / 64, 256, SM_GATE>>>(x, gW1, gb1, gW2, gb2);
        k_gmax<<<TB(N_), 256>>>(bat);
        k_expsum<<<TB(N_), 256>>>(bat, side);
        k_attsum<<<TB(N_ * 16), 256>>>(x, bat, side);
    }

    // ---- GCN stacks ----
    for (int side = 0; side < 2; ++side) {
        const float* x   = side ? x_d : x_p;
        const int*   ei  = side ? ei_d : ei_p;
        const int*   bat = side ? bat_d : bat_p;
        const int* src = ei;
        const int* dst = ei + E_;

        // CSR build (by dst) + dinv
        k_csr_init<<<TB(N_), 256>>>();
        k_count<<<TB(E_), 256>>>(dst);
        k_scan1<<<NTILES_, 1024>>>();
        k_scan2<<<1, 512>>>();
        k_scan3<<<TB(N_), 256>>>();
        k_fill<<<TB(E_), 256>>>(src, dst);
        k_dinv<<<TB(N_), 256>>>();

        // fused agg+GEMM layers (agg(x)W == agg(xW))
        k_layer<64, true, -1><<<N_ / 64, 256, SM_L64>>>(x, convW[side][0], convB[side][0], bufA, nullptr);
        k_layer<96, true, -1><<<N_ / 64, 256, SM_L96>>>(bufA, convW[side][1], convB[side][1], bufB, nullptr);
        if (side == 0)
            k_layer<96, false, 0><<<N_ / 64, 256, SM_L96>>>(bufB, convW[side][2], convB[side][2], bufA, bat);
        else
            k_layer<96, false, 1><<<N_ / 64, 256, SM_L96>>>(bufB, convW[side][2], convB[side][2], bufA, bat);
    }

    // ---- final MLP ----
    k_final<<<B_, 128>>>(lW0, lb0, lW1, lb1, out);
}

// round 5
// speedup vs baseline: 1.6603x; 1.5996x over previous
#include <cuda_runtime.h>
#include <cstddef>

// Problem constants
#define N_ 400000
#define E_ 1600000
#define B_ 8192
#define F_ 64
#define H_ 96
#define NTILES_ ((N_ + 1023) / 1024)   // 391

// ---------------- scratch (device globals; no allocations allowed) ----------------
__device__ float g_bufA[(size_t)N_ * H_];
__device__ float g_bufB[(size_t)N_ * H_];
__device__ float g_dinv[N_];
__device__ int   g_deg[N_];
__device__ int   g_rowptr[N_ + 1];
__device__ int   g_fill[N_];
__device__ int   g_csr[E_];
__device__ int   g_bsum[NTILES_];
__device__ float g_gate[N_];
__device__ int   g_boffs[2][B_ + 1];   // batch segment offsets (lower bounds)
__device__ float g_att [2][B_ * F_];
__device__ float g_psum[2][B_ * H_];   // pooled sums of agg(bufB)
__device__ float g_mean[2][B_ * H_];   // (psum/cnt) @ W2 + b2

// packed fp32x2 FMA (Blackwell FFMA2 — only reachable via PTX)
__device__ __forceinline__ float2 ffma2(float2 a, float2 b, float2 c) {
    unsigned long long A = *reinterpret_cast<unsigned long long*>(&a);
    unsigned long long Bv = *reinterpret_cast<unsigned long long*>(&b);
    unsigned long long C = *reinterpret_cast<unsigned long long*>(&c);
    unsigned long long D;
    asm("fma.rn.f32x2 %0, %1, %2, %3;" : "=l"(D) : "l"(A), "l"(Bv), "l"(C));
    return *reinterpret_cast<float2*>(&D);
}

// ---------------- gate MLP: g = relu(x@W1+b1)@W2 + b2 (f32x2 GEMM) ----------------
__global__ void k_gate(const float* __restrict__ x, const float* __restrict__ W1,
                       const float* __restrict__ b1, const float* __restrict__ W2,
                       const float* __restrict__ b2) {
    extern __shared__ char sm_raw[];
    float*  xT  = (float*)sm_raw;
    float2* W1d = (float2*)(sm_raw + 64 * 68 * 4);
    float*  b1s = (float*)(sm_raw + 64 * 68 * 4 + 64 * 64 * 8);
    float*  W2s = b1s + 64;
    int tid = threadIdx.x;
    int row0 = blockIdx.x * 64;

    for (int i = tid; i < 64 * 64; i += 256) {
        float w = W1[i];
        W1d[i] = make_float2(w, w);
    }
    if (tid < 64) { b1s[tid] = b1[tid]; W2s[tid] = W2[tid]; }
    {
        int g = tid >> 2, l = tid & 3;
        const float4* sp = (const float4*)(x + (size_t)(row0 + g) * 64) + l * 4;
#pragma unroll
        for (int j = 0; j < 4; ++j) {
            float4 v = sp[j];
            int k = l * 16 + j * 4;
            xT[(k + 0) * 68 + g] = v.x;
            xT[(k + 1) * 68 + g] = v.y;
            xT[(k + 2) * 68 + g] = v.z;
            xT[(k + 3) * 68 + g] = v.w;
        }
    }
    __syncthreads();

    int cg = tid & 15, rg = tid >> 4;
    int r0 = rg * 4, u0 = cg * 4;
    float2 acc2[2][4];
#pragma unroll
    for (int p = 0; p < 2; ++p)
#pragma unroll
        for (int c = 0; c < 4; ++c) acc2[p][c] = make_float2(0.f, 0.f);
#pragma unroll 4
    for (int k = 0; k < 64; ++k) {
        float2 a0 = *(const float2*)&xT[k * 68 + r0];
        float2 a1 = *(const float2*)&xT[k * 68 + r0 + 2];
#pragma unroll
        for (int c = 0; c < 4; ++c) {
            float2 w = W1d[k * 64 + u0 + c];
            acc2[0][c] = ffma2(a0, w, acc2[0][c]);
            acc2[1][c] = ffma2(a1, w, acc2[1][c]);
        }
    }
    float sr[4];
#pragma unroll
    for (int p = 0; p < 2; ++p) {
        float sx = 0.f, sy = 0.f;
#pragma unroll
        for (int c = 0; c < 4; ++c) {
            float bb = b1s[u0 + c], w2 = W2s[u0 + c];
            sx += fmaxf(acc2[p][c].x + bb, 0.f) * w2;
            sy += fmaxf(acc2[p][c].y + bb, 0.f) * w2;
        }
        sr[2 * p] = sx; sr[2 * p + 1] = sy;
    }
#pragma unroll
    for (int o = 8; o > 0; o >>= 1)
#pragma unroll
        for (int i = 0; i < 4; ++i)
            sr[i] += __shfl_xor_sync(0xffffffffu, sr[i], o, 16);
    if (cg == 0) {
        float bb = b2[0];
#pragma unroll
        for (int i = 0; i < 4; ++i) g_gate[row0 + r0 + i] = sr[i] + bb;
    }
}

// ---------------- batch segment offsets (batch is sorted) ----------------
__global__ void k_boffs(const int* __restrict__ batch, int side) {
    int i = blockIdx.x * blockDim.x + threadIdx.x;
    if (i >= N_) return;
    int b = batch[i];
    if (i == 0) {
        for (int bb = 0; bb <= b; ++bb) g_boffs[side][bb] = 0;
    } else {
        int pb = batch[i - 1];
        for (int bb = pb + 1; bb <= b; ++bb) g_boffs[side][bb] = i;
    }
    if (i == N_ - 1) {
        for (int bb = b + 1; bb <= B_; ++bb) g_boffs[side][bb] = N_;
    }
}

// ---------------- attention pool: one block per batch segment, no atomics ----------------
__global__ void k_att(const float* __restrict__ x, int side) {
    __shared__ float sred[256];
    __shared__ float red[64][64];
    int b = blockIdx.x, tid = threadIdx.x;
    int start = g_boffs[side][b], end = g_boffs[side][b + 1];

    // segment max
    float m = -1e30f;
    for (int i = start + tid; i < end; i += 256) m = fmaxf(m, g_gate[i]);
    sred[tid] = m;
    __syncthreads();
    for (int o = 128; o > 0; o >>= 1) {
        if (tid < o) sred[tid] = fmaxf(sred[tid], sred[tid + o]);
        __syncthreads();
    }
    float gmax = sred[0];
    __syncthreads();

    // denom
    float s = 0.f;
    for (int i = start + tid; i < end; i += 256) s += expf(g_gate[i] - gmax);
    sred[tid] = s;
    __syncthreads();
    for (int o = 128; o > 0; o >>= 1) {
        if (tid < o) sred[tid] += sred[tid + o];
        __syncthreads();
    }
    float denom = sred[0];

    // weighted sum of x (64 floats; 4 lanes x 16 floats)
    int slot = tid >> 2, l = tid & 3;
    float4 acc[4];
#pragma unroll
    for (int j = 0; j < 4; ++j) acc[j] = make_float4(0.f, 0.f, 0.f, 0.f);
    for (int i = start + slot; i < end; i += 64) {
        float e = expf(g_gate[i] - gmax);
        const float4* xp = (const float4*)(x + (size_t)i * 64) + l * 4;
#pragma unroll
        for (int j = 0; j < 4; ++j) {
            float4 v = xp[j];
            acc[j].x += e * v.x; acc[j].y += e * v.y;
            acc[j].z += e * v.z; acc[j].w += e * v.w;
        }
    }
#pragma unroll
    for (int j = 0; j < 4; ++j) *(float4*)&red[slot][l * 16 + j * 4] = acc[j];
    __syncthreads();
    for (int o = 32; o > 0; o >>= 1) {
        if (slot < o) {
#pragma unroll
            for (int j = 0; j < 4; ++j) {
                float4 a = *(float4*)&red[slot][l * 16 + j * 4];
                float4 c = *(float4*)&red[slot + o][l * 16 + j * 4];
                a.x += c.x; a.y += c.y; a.z += c.z; a.w += c.w;
                *(float4*)&red[slot][l * 16 + j * 4] = a;
            }
        }
        __syncthreads();
    }
    if (slot == 0) {
        float inv = (end > start) ? 1.f / denom : 0.f;
#pragma unroll
        for (int j = 0; j < 16; ++j)
            g_att[side][(size_t)b * 64 + l * 16 + j] = red[0][l * 16 + j] * inv;
    }
}

// ---------------- CSR build (counting sort by dst) ----------------
__global__ void k_csr_init() {
    int i = blockIdx.x * blockDim.x + threadIdx.x;
    if (i < N_) { g_deg[i] = 0; g_fill[i] = 0; }
}
__global__ void k_count(const int* __restrict__ dst) {
    int e = blockIdx.x * blockDim.x + threadIdx.x;
    if (e < E_) atomicAdd(&g_deg[dst[e]], 1);
}
__global__ void k_scan1() {
    __shared__ int s[1024];
    int tx = threadIdx.x;
    int i = blockIdx.x * 1024 + tx;
    int v = (i < N_) ? g_deg[i] : 0;
    s[tx] = v;
    __syncthreads();
    for (int o = 1; o < 1024; o <<= 1) {
        int t = (tx >= o) ? s[tx - o] : 0;
        __syncthreads();
        s[tx] += t;
        __syncthreads();
    }
    if (i < N_) g_rowptr[i] = s[tx] - v;
    if (tx == 1023) g_bsum[blockIdx.x] = s[1023];
}
__global__ void k_scan2() {
    __shared__ int s[512];
    int tx = threadIdx.x;
    int v = (tx < NTILES_) ? g_bsum[tx] : 0;
    s[tx] = v;
    __syncthreads();
    for (int o = 1; o < 512; o <<= 1) {
        int t = (tx >= o) ? s[tx - o] : 0;
        __syncthreads();
        s[tx] += t;
        __syncthreads();
    }
    if (tx < NTILES_) g_bsum[tx] = s[tx] - v;
}
__global__ void k_scan3() {
    int i = blockIdx.x * blockDim.x + threadIdx.x;
    if (i < N_) g_rowptr[i] += g_bsum[i >> 10];
    if (i == 0) g_rowptr[N_] = E_;
}
__global__ void k_fill(const int* __restrict__ src, const int* __restrict__ dst) {
    int e = blockIdx.x * blockDim.x + threadIdx.x;
    if (e >= E_) return;
    int d = dst[e];
    int pos = g_rowptr[d] + atomicAdd(&g_fill[d], 1);
    g_csr[pos] = src[e];
}
__global__ void k_dinv() {
    int i = blockIdx.x * blockDim.x + threadIdx.x;
    if (i < N_) g_dinv[i] = rsqrtf((float)(g_deg[i] + 1));
}

// ---------------- fused layer: out = relu?(agg(in) @ W + b) ----------------
// block = 64 dst rows, 256 threads.
// dyn smem: As[FIN][68] (transposed agg) | Ws[FIN*96] (plain) | bs[96]
template <int FIN, bool RELU>
__global__ void k_layer(const float* __restrict__ in, const float* __restrict__ W,
                        const float* __restrict__ bias, float* __restrict__ out) {
    constexpr int VT = FIN / 16;    // float4 per gather thread (4 threads/node)
    extern __shared__ char sm_raw[];
    float* As = (float*)sm_raw;
    float* Ws = As + FIN * 68;
    float* bs = Ws + FIN * 96;
    int tid = threadIdx.x;
    int row0 = blockIdx.x * 64;

    for (int i = tid; i < FIN * 96 / 4; i += 256)
        *(float4*)&Ws[i * 4] = *(const float4*)&W[i * 4];
    if (tid < 96) bs[tid] = bias[tid];

    // ---- gather phase: agg = dinv_d^2 * x_d + sum_nbr dinv_s*dinv_d * x_s ----
    {
        int g = tid >> 2, l = tid & 3;
        int node = row0 + g;
        float dn = g_dinv[node];
        float sc = dn * dn;
        float4 acc[VT];
        const float4* sp = (const float4*)(in + (size_t)node * FIN) + l * VT;
#pragma unroll
        for (int j = 0; j < VT; ++j) {
            float4 v = sp[j];
            acc[j] = make_float4(v.x * sc, v.y * sc, v.z * sc, v.w * sc);
        }
        int p1 = g_rowptr[node + 1];
        for (int p = g_rowptr[node]; p < p1; ++p) {
            int s = g_csr[p];
            float nrm = g_dinv[s] * dn;
            const float4* np = (const float4*)(in + (size_t)s * FIN) + l * VT;
#pragma unroll
            for (int j = 0; j < VT; ++j) {
                float4 v = np[j];
                acc[j].x += v.x * nrm; acc[j].y += v.y * nrm;
                acc[j].z += v.z * nrm; acc[j].w += v.w * nrm;
            }
        }
#pragma unroll
        for (int j = 0; j < VT; ++j) {
            int k = l * (VT * 4) + j * 4;
            As[(k + 0) * 68 + g] = acc[j].x;
            As[(k + 1) * 68 + g] = acc[j].y;
            As[(k + 2) * 68 + g] = acc[j].z;
            As[(k + 3) * 68 + g] = acc[j].w;
        }
    }
    __syncthreads();

    // ---- GEMM phase: [64 x FIN] @ [FIN x 96], 4 rows x 3 col-pairs via f32x2 ----
    int rg = tid & 15, cg = tid >> 4;
    int r0 = rg * 4, c0 = cg * 6;
    float2 acc2[4][3];
#pragma unroll
    for (int r = 0; r < 4; ++r)
#pragma unroll
        for (int c = 0; c < 3; ++c) acc2[r][c] = make_float2(0.f, 0.f);
#pragma unroll 4
    for (int k = 0; k < FIN; ++k) {
        float4 av = *(const float4*)&As[k * 68 + r0];
        float2 w0 = *(const float2*)&Ws[k * 96 + c0];
        float2 w1 = *(const float2*)&Ws[k * 96 + c0 + 2];
        float2 w2 = *(const float2*)&Ws[k * 96 + c0 + 4];
        float ar[4] = {av.x, av.y, av.z, av.w};
#pragma unroll
        for (int r = 0; r < 4; ++r) {
            float2 ad = make_float2(ar[r], ar[r]);
            acc2[r][0] = ffma2(ad, w0, acc2[r][0]);
            acc2[r][1] = ffma2(ad, w1, acc2[r][1]);
            acc2[r][2] = ffma2(ad, w2, acc2[r][2]);
        }
    }

    // ---- epilogue ----
#pragma unroll
    for (int r = 0; r < 4; ++r) {
        int row = row0 + r0 + r;
#pragma unroll
        for (int c = 0; c < 3; ++c) {
            int col = c0 + 2 * c;
            float2 v = acc2[r][c];
            v.x += bs[col]; v.y += bs[col + 1];
            if (RELU) { v.x = fmaxf(v.x, 0.f); v.y = fmaxf(v.y, 0.f); }
            *(float2*)&out[(size_t)row * 96 + col] = v;
        }
    }
}

// ---------------- layer-3 pooled aggregation: g_psum[b] = sum_{i in b} agg(in)_i ----------------
// one block per batch segment; no GEMM (deferred), no atomics.
__global__ void k_pool3(const float* __restrict__ in, int side) {
    __shared__ float red[64][96];
    int b = blockIdx.x, tid = threadIdx.x;
    int start = g_boffs[side][b], end = g_boffs[side][b + 1];
    int slot = tid >> 2, l = tid & 3;
    float4 acc[6];
#pragma unroll
    for (int j = 0; j < 6; ++j) acc[j] = make_float4(0.f, 0.f, 0.f, 0.f);

    for (int node = start + slot; node < end; node += 64) {
        float dn = g_dinv[node];
        float sc = dn * dn;
        const float4* sp = (const float4*)(in + (size_t)node * 96) + l * 6;
#pragma unroll
        for (int j = 0; j < 6; ++j) {
            float4 v = sp[j];
            acc[j].x += v.x * sc; acc[j].y += v.y * sc;
            acc[j].z += v.z * sc; acc[j].w += v.w * sc;
        }
        int p1 = g_rowptr[node + 1];
        for (int p = g_rowptr[node]; p < p1; ++p) {
            int s = g_csr[p];
            float nrm = g_dinv[s] * dn;
            const float4* np = (const float4*)(in + (size_t)s * 96) + l * 6;
#pragma unroll
            for (int j = 0; j < 6; ++j) {
                float4 v = np[j];
                acc[j].x += v.x * nrm; acc[j].y += v.y * nrm;
                acc[j].z += v.z * nrm; acc[j].w += v.w * nrm;
            }
        }
    }
#pragma unroll
    for (int j = 0; j < 6; ++j) *(float4*)&red[slot][l * 24 + j * 4] = acc[j];
    __syncthreads();
    for (int o = 32; o > 0; o >>= 1) {
        if (slot < o) {
#pragma unroll
            for (int j = 0; j < 6; ++j) {
                float4 a = *(float4*)&red[slot][l * 24 + j * 4];
                float4 c = *(float4*)&red[slot + o][l * 24 + j * 4];
                a.x += c.x; a.y += c.y; a.z += c.z; a.w += c.w;
                *(float4*)&red[slot][l * 24 + j * 4] = a;
            }
        }
        __syncthreads();
    }
    if (slot == 0) {
#pragma unroll
        for (int j = 0; j < 6; ++j)
            *(float4*)&g_psum[side][(size_t)b * 96 + l * 24 + j * 4] =
                *(float4*)&red[0][l * 24 + j * 4];
    }
}

// ---------------- deferred layer-3 GEMM on pooled means: g_mean = (psum/cnt)@W + b ----------------
__global__ void k_small(const float* __restrict__ W, const float* __restrict__ bias, int side) {
    __shared__ float inp[96];
    int b = blockIdx.x, c = threadIdx.x;   // 96 threads
    int cnt = g_boffs[side][b + 1] - g_boffs[side][b];
    float ic = 1.f / fmaxf((float)cnt, 1.f);
    inp[c] = g_psum[side][(size_t)b * 96 + c] * ic;
    __syncthreads();
    float acc = bias[c];
#pragma unroll 4
    for (int k = 0; k < 96; ++k) acc += inp[k] * W[k * 96 + c];
    g_mean[side][(size_t)b * 96 + c] = acc;
}

// ---------------- final MLP: one block per batch row ----------------
__global__ void k_final(const float* __restrict__ W0, const float* __restrict__ b0,
                        const float* __restrict__ W1, const float* __restrict__ b1,
                        float* __restrict__ out) {
    __shared__ float in[320];
    __shared__ float red[128];
    int b = blockIdx.x, t = threadIdx.x;   // 128 threads
    for (int i = t; i < 96; i += 128) {
        in[i]      = g_mean[0][(size_t)b * 96 + i];
        in[96 + i] = g_mean[1][(size_t)b * 96 + i];
    }
    for (int i = t; i < 64; i += 128) {
        in[192 + i] = g_att[0][(size_t)b * 64 + i];
        in[256 + i] = g_att[1][(size_t)b * 64 + i];
    }
    __syncthreads();
    float p = 0.f;
    if (t < 96) {
        float acc = b0[t];
        for (int k = 0; k < 320; ++k) acc += in[k] * W0[(size_t)k * 96 + t];
        p = fmaxf(acc, 0.f) * W1[t];
    }
    red[t] = p;
    __syncthreads();
    for (int s = 64; s > 0; s >>= 1) {
        if (t < s) red[t] += red[t + s];
        __syncthreads();
    }
    if (t == 0) out[b] = red[0] + b1[0];
}

// ---------------- launch ----------------
static inline int TB(int n) { return (n + 255) / 256; }

extern "C" void kernel_launch(void* const* d_in, const int* in_sizes, int n_in,
                              void* d_out, int out_size) {
    const float* x_p   = (const float*)d_in[0];
    const float* x_d   = (const float*)d_in[1];
    // d_in[2], d_in[3]: edge_attr — unused
    const int*   ei_p  = (const int*)d_in[4];
    const int*   ei_d  = (const int*)d_in[5];
    const int*   bat_p = (const int*)d_in[6];
    const int*   bat_d = (const int*)d_in[7];
    const float* gW1 = (const float*)d_in[8];
    const float* gb1 = (const float*)d_in[9];
    const float* gW2 = (const float*)d_in[10];
    const float* gb2 = (const float*)d_in[11];
    const float* convW[2][3] = {
        {(const float*)d_in[12], (const float*)d_in[14], (const float*)d_in[16]},
        {(const float*)d_in[18], (const float*)d_in[20], (const float*)d_in[22]}};
    const float* convB[2][3] = {
        {(const float*)d_in[13], (const float*)d_in[15], (const float*)d_in[17]},
        {(const float*)d_in[19], (const float*)d_in[21], (const float*)d_in[23]}};
    const float* lW0 = (const float*)d_in[24];
    const float* lb0 = (const float*)d_in[25];
    const float* lW1 = (const float*)d_in[26];
    const float* lb1 = (const float*)d_in[27];
    float* out = (float*)d_out;

    float *bufA, *bufB;
    cudaGetSymbolAddress((void**)&bufA, g_bufA);
    cudaGetSymbolAddress((void**)&bufB, g_bufB);

    const int SM_L64  = (64 * 68 + 64 * 96 + 96) * 4;           // 42368
    const int SM_L96  = (96 * 68 + 96 * 96 + 96) * 4;           // 63360
    const int SM_GATE = 64 * 68 * 4 + 64 * 64 * 8 + 2 * 64 * 4; // 50688
    cudaFuncSetAttribute(k_layer<64, true>, cudaFuncAttributeMaxDynamicSharedMemorySize, SM_L64);
    cudaFuncSetAttribute(k_layer<96, true>, cudaFuncAttributeMaxDynamicSharedMemorySize, SM_L96);
    cudaFuncSetAttribute(k_gate, cudaFuncAttributeMaxDynamicSharedMemorySize, SM_GATE);

    for (int side = 0; side < 2; ++side) {
        const float* x   = side ? x_d : x_p;
        const int*   ei  = side ? ei_d : ei_p;
        const int*   bat = side ? bat_d : bat_p;
        const int* src = ei;
        const int* dst = ei + E_;

        // ---- attention pool (raw x) ----
        k_gate<<<N_ / 64, 256, SM_GATE>>>(x, gW1, gb1, gW2, gb2);
        k_boffs<<<TB(N_), 256>>>(bat, side);
        k_att<<<B_, 256>>>(x, side);

        // ---- CSR build (by dst) + dinv ----
        k_csr_init<<<TB(N_), 256>>>();
        k_count<<<TB(E_), 256>>>(dst);
        k_scan1<<<NTILES_, 1024>>>();
        k_scan2<<<1, 512>>>();
        k_scan3<<<TB(N_), 256>>>();
        k_fill<<<TB(E_), 256>>>(src, dst);
        k_dinv<<<TB(N_), 256>>>();

        // ---- fused agg+GEMM layers 1-2, pooled layer 3 ----
        k_layer<64, true><<<N_ / 64, 256, SM_L64>>>(x, convW[side][0], convB[side][0], bufA);
        k_layer<96, true><<<N_ / 64, 256, SM_L96>>>(bufA, convW[side][1], convB[side][1], bufB);
        k_pool3<<<B_, 256>>>(bufB, side);
        k_small<<<B_, 96>>>(convW[side][2], convB[side][2], side);
    }

    // ---- final MLP ----
    k_final<<<B_, 128>>>(lW0, lb0, lW1, lb1, out);
}

// round 6
// speedup vs baseline: 1.9198x; 1.1563x over previous
#include <cuda_runtime.h>
#include <cuda_bf16.h>
#include <cstddef>

// Problem constants
#define N_ 400000
#define E_ 1600000
#define B_ 8192
#define F_ 64
#define H_ 96
#define NTILES_ ((N_ + 1023) / 1024)   // 391

// ---------------- scratch (device globals; no allocations allowed) ----------------
__device__ __nv_bfloat16 g_bufA[(size_t)N_ * H_];   // 76.8 MB (L2-resident)
__device__ __nv_bfloat16 g_bufB[(size_t)N_ * H_];   // 76.8 MB (L2-resident)
__device__ float g_dinv[N_];
__device__ int   g_deg[N_];
__device__ int   g_rowptr[N_ + 1];
__device__ int   g_fill[N_];
__device__ int   g_csr[E_];
__device__ int   g_bsum[NTILES_];
__device__ float g_gate[N_];
__device__ int   g_boffs[2][B_ + 1];   // batch segment offsets (lower bounds)
__device__ float g_att [2][B_ * F_];
__device__ float g_psum[2][B_ * H_];   // pooled sums of agg(bufB)
__device__ float g_mean[2][B_ * H_];   // (psum/cnt) @ W2 + b2

// packed fp32x2 FMA (Blackwell FFMA2 — only reachable via PTX)
__device__ __forceinline__ float2 ffma2(float2 a, float2 b, float2 c) {
    unsigned long long A = *reinterpret_cast<unsigned long long*>(&a);
    unsigned long long Bv = *reinterpret_cast<unsigned long long*>(&b);
    unsigned long long C = *reinterpret_cast<unsigned long long*>(&c);
    unsigned long long D;
    asm("fma.rn.f32x2 %0, %1, %2, %3;" : "=l"(D) : "l"(A), "l"(Bv), "l"(C));
    return *reinterpret_cast<float2*>(&D);
}

// ---------------- gate MLP: g = relu(x@W1+b1)@W2 + b2 (f32x2 GEMM) ----------------
__global__ void k_gate(const float* __restrict__ x, const float* __restrict__ W1,
                       const float* __restrict__ b1, const float* __restrict__ W2,
                       const float* __restrict__ b2) {
    extern __shared__ char sm_raw[];
    float*  xT  = (float*)sm_raw;
    float2* W1d = (float2*)(sm_raw + 64 * 68 * 4);
    float*  b1s = (float*)(sm_raw + 64 * 68 * 4 + 64 * 64 * 8);
    float*  W2s = b1s + 64;
    int tid = threadIdx.x;
    int row0 = blockIdx.x * 64;

    for (int i = tid; i < 64 * 64; i += 256) {
        float w = W1[i];
        W1d[i] = make_float2(w, w);
    }
    if (tid < 64) { b1s[tid] = b1[tid]; W2s[tid] = W2[tid]; }
    {
        int g = tid >> 2, l = tid & 3;
        const float4* sp = (const float4*)(x + (size_t)(row0 + g) * 64) + l * 4;
#pragma unroll
        for (int j = 0; j < 4; ++j) {
            float4 v = sp[j];
            int k = l * 16 + j * 4;
            xT[(k + 0) * 68 + g] = v.x;
            xT[(k + 1) * 68 + g] = v.y;
            xT[(k + 2) * 68 + g] = v.z;
            xT[(k + 3) * 68 + g] = v.w;
        }
    }
    __syncthreads();

    int cg = tid & 15, rg = tid >> 4;
    int r0 = rg * 4, u0 = cg * 4;
    float2 acc2[2][4];
#pragma unroll
    for (int p = 0; p < 2; ++p)
#pragma unroll
        for (int c = 0; c < 4; ++c) acc2[p][c] = make_float2(0.f, 0.f);
#pragma unroll 4
    for (int k = 0; k < 64; ++k) {
        float2 a0 = *(const float2*)&xT[k * 68 + r0];
        float2 a1 = *(const float2*)&xT[k * 68 + r0 + 2];
#pragma unroll
        for (int c = 0; c < 4; ++c) {
            float2 w = W1d[k * 64 + u0 + c];
            acc2[0][c] = ffma2(a0, w, acc2[0][c]);
            acc2[1][c] = ffma2(a1, w, acc2[1][c]);
        }
    }
    float sr[4];
#pragma unroll
    for (int p = 0; p < 2; ++p) {
        float sx = 0.f, sy = 0.f;
#pragma unroll
        for (int c = 0; c < 4; ++c) {
            float bb = b1s[u0 + c], w2 = W2s[u0 + c];
            sx += fmaxf(acc2[p][c].x + bb, 0.f) * w2;
            sy += fmaxf(acc2[p][c].y + bb, 0.f) * w2;
        }
        sr[2 * p] = sx; sr[2 * p + 1] = sy;
    }
#pragma unroll
    for (int o = 8; o > 0; o >>= 1)
#pragma unroll
        for (int i = 0; i < 4; ++i)
            sr[i] += __shfl_xor_sync(0xffffffffu, sr[i], o, 16);
    if (cg == 0) {
        float bb = b2[0];
#pragma unroll
        for (int i = 0; i < 4; ++i) g_gate[row0 + r0 + i] = sr[i] + bb;
    }
}

// ---------------- batch segment offsets (batch is sorted) ----------------
__global__ void k_boffs(const int* __restrict__ batch, int side) {
    int i = blockIdx.x * blockDim.x + threadIdx.x;
    if (i >= N_) return;
    int b = batch[i];
    if (i == 0) {
        for (int bb = 0; bb <= b; ++bb) g_boffs[side][bb] = 0;
    } else {
        int pb = batch[i - 1];
        for (int bb = pb + 1; bb <= b; ++bb) g_boffs[side][bb] = i;
    }
    if (i == N_ - 1) {
        for (int bb = b + 1; bb <= B_; ++bb) g_boffs[side][bb] = N_;
    }
}

// ---------------- attention pool: one block per batch segment, no atomics ----------------
__global__ void k_att(const float* __restrict__ x, int side) {
    __shared__ float sred[256];
    __shared__ float red[64][64];
    int b = blockIdx.x, tid = threadIdx.x;
    int start = g_boffs[side][b], end = g_boffs[side][b + 1];

    // segment max
    float m = -1e30f;
    for (int i = start + tid; i < end; i += 256) m = fmaxf(m, g_gate[i]);
    sred[tid] = m;
    __syncthreads();
    for (int o = 128; o > 0; o >>= 1) {
        if (tid < o) sred[tid] = fmaxf(sred[tid], sred[tid + o]);
        __syncthreads();
    }
    float gmax = sred[0];
    __syncthreads();

    // denom
    float s = 0.f;
    for (int i = start + tid; i < end; i += 256) s += expf(g_gate[i] - gmax);
    sred[tid] = s;
    __syncthreads();
    for (int o = 128; o > 0; o >>= 1) {
        if (tid < o) sred[tid] += sred[tid + o];
        __syncthreads();
    }
    float denom = sred[0];

    // weighted sum of x (64 floats; 4 lanes x 16 floats)
    int slot = tid >> 2, l = tid & 3;
    float4 acc[4];
#pragma unroll
    for (int j = 0; j < 4; ++j) acc[j] = make_float4(0.f, 0.f, 0.f, 0.f);
    for (int i = start + slot; i < end; i += 64) {
        float e = expf(g_gate[i] - gmax);
        const float4* xp = (const float4*)(x + (size_t)i * 64) + l * 4;
#pragma unroll
        for (int j = 0; j < 4; ++j) {
            float4 v = xp[j];
            acc[j].x += e * v.x; acc[j].y += e * v.y;
            acc[j].z += e * v.z; acc[j].w += e * v.w;
        }
    }
#pragma unroll
    for (int j = 0; j < 4; ++j) *(float4*)&red[slot][l * 16 + j * 4] = acc[j];
    __syncthreads();
    for (int o = 32; o > 0; o >>= 1) {
        if (slot < o) {
#pragma unroll
            for (int j = 0; j < 4; ++j) {
                float4 a = *(float4*)&red[slot][l * 16 + j * 4];
                float4 c = *(float4*)&red[slot + o][l * 16 + j * 4];
                a.x += c.x; a.y += c.y; a.z += c.z; a.w += c.w;
                *(float4*)&red[slot][l * 16 + j * 4] = a;
            }
        }
        __syncthreads();
    }
    if (slot == 0) {
        float inv = (end > start) ? 1.f / denom : 0.f;
#pragma unroll
        for (int j = 0; j < 16; ++j)
            g_att[side][(size_t)b * 64 + l * 16 + j] = red[0][l * 16 + j] * inv;
    }
}

// ---------------- CSR build (counting sort by dst) ----------------
__global__ void k_csr_init() {
    int i = blockIdx.x * blockDim.x + threadIdx.x;
    if (i < N_) { g_deg[i] = 0; g_fill[i] = 0; }
}
__global__ void k_count(const int* __restrict__ dst) {
    int e = blockIdx.x * blockDim.x + threadIdx.x;
    if (e < E_) atomicAdd(&g_deg[dst[e]], 1);
}
__global__ void k_scan1() {
    __shared__ int s[1024];
    int tx = threadIdx.x;
    int i = blockIdx.x * 1024 + tx;
    int v = (i < N_) ? g_deg[i] : 0;
    s[tx] = v;
    __syncthreads();
    for (int o = 1; o < 1024; o <<= 1) {
        int t = (tx >= o) ? s[tx - o] : 0;
        __syncthreads();
        s[tx] += t;
        __syncthreads();
    }
    if (i < N_) g_rowptr[i] = s[tx] - v;
    if (tx == 1023) g_bsum[blockIdx.x] = s[1023];
}
__global__ void k_scan2() {
    __shared__ int s[512];
    int tx = threadIdx.x;
    int v = (tx < NTILES_) ? g_bsum[tx] : 0;
    s[tx] = v;
    __syncthreads();
    for (int o = 1; o < 512; o <<= 1) {
        int t = (tx >= o) ? s[tx - o] : 0;
        __syncthreads();
        s[tx] += t;
        __syncthreads();
    }
    if (tx < NTILES_) g_bsum[tx] = s[tx] - v;
}
__global__ void k_scan3() {
    int i = blockIdx.x * blockDim.x + threadIdx.x;
    if (i < N_) g_rowptr[i] += g_bsum[i >> 10];
    if (i == 0) g_rowptr[N_] = E_;
}
__global__ void k_fill(const int* __restrict__ src, const int* __restrict__ dst) {
    int e = blockIdx.x * blockDim.x + threadIdx.x;
    if (e >= E_) return;
    int d = dst[e];
    int pos = g_rowptr[d] + atomicAdd(&g_fill[d], 1);
    g_csr[pos] = src[e];
}
__global__ void k_dinv() {
    int i = blockIdx.x * blockDim.x + threadIdx.x;
    if (i < N_) g_dinv[i] = rsqrtf((float)(g_deg[i] + 1));
}

// ---------------- layer 1: out_bf16 = relu(agg(x_fp32) @ W + b) ----------------
// block = 64 dst rows, 256 threads. smem: As[64][68] | Ws[64*96] | bs[96]
__global__ void k_layer1(const float* __restrict__ in, const float* __restrict__ W,
                         const float* __restrict__ bias, __nv_bfloat16* __restrict__ out) {
    extern __shared__ char sm_raw[];
    float* As = (float*)sm_raw;
    float* Ws = As + 64 * 68;
    float* bs = Ws + 64 * 96;
    int tid = threadIdx.x;
    int row0 = blockIdx.x * 64;

    for (int i = tid; i < 64 * 96 / 4; i += 256)
        *(float4*)&Ws[i * 4] = *(const float4*)&W[i * 4];
    if (tid < 96) bs[tid] = bias[tid];

    // gather: agg = dinv_d^2 * x_d + sum_nbr dinv_s*dinv_d * x_s (fp32 input)
    {
        int g = tid >> 2, l = tid & 3;
        int node = row0 + g;
        float dn = g_dinv[node];
        float sc = dn * dn;
        float4 acc[4];
        const float4* sp = (const float4*)(in + (size_t)node * 64) + l * 4;
#pragma unroll
        for (int j = 0; j < 4; ++j) {
            float4 v = sp[j];
            acc[j] = make_float4(v.x * sc, v.y * sc, v.z * sc, v.w * sc);
        }
        int p1 = g_rowptr[node + 1];
        for (int p = g_rowptr[node]; p < p1; ++p) {
            int s = g_csr[p];
            float nrm = g_dinv[s] * dn;
            const float4* np = (const float4*)(in + (size_t)s * 64) + l * 4;
#pragma unroll
            for (int j = 0; j < 4; ++j) {
                float4 v = np[j];
                acc[j].x += v.x * nrm; acc[j].y += v.y * nrm;
                acc[j].z += v.z * nrm; acc[j].w += v.w * nrm;
            }
        }
#pragma unroll
        for (int j = 0; j < 4; ++j) {
            int k = l * 16 + j * 4;
            As[(k + 0) * 68 + g] = acc[j].x;
            As[(k + 1) * 68 + g] = acc[j].y;
            As[(k + 2) * 68 + g] = acc[j].z;
            As[(k + 3) * 68 + g] = acc[j].w;
        }
    }
    __syncthreads();

    // GEMM: [64 x 64] @ [64 x 96], 4 rows x 3 col-pairs via f32x2
    int rg = tid & 15, cg = tid >> 4;
    int r0 = rg * 4, c0 = cg * 6;
    float2 acc2[4][3];
#pragma unroll
    for (int r = 0; r < 4; ++r)
#pragma unroll
        for (int c = 0; c < 3; ++c) acc2[r][c] = make_float2(0.f, 0.f);
#pragma unroll 4
    for (int k = 0; k < 64; ++k) {
        float4 av = *(const float4*)&As[k * 68 + r0];
        float2 w0 = *(const float2*)&Ws[k * 96 + c0];
        float2 w1 = *(const float2*)&Ws[k * 96 + c0 + 2];
        float2 w2 = *(const float2*)&Ws[k * 96 + c0 + 4];
        float ar[4] = {av.x, av.y, av.z, av.w};
#pragma unroll
        for (int r = 0; r < 4; ++r) {
            float2 ad = make_float2(ar[r], ar[r]);
            acc2[r][0] = ffma2(ad, w0, acc2[r][0]);
            acc2[r][1] = ffma2(ad, w1, acc2[r][1]);
            acc2[r][2] = ffma2(ad, w2, acc2[r][2]);
        }
    }

    // epilogue: relu + bf16 pack
#pragma unroll
    for (int r = 0; r < 4; ++r) {
        int row = row0 + r0 + r;
#pragma unroll
        for (int c = 0; c < 3; ++c) {
            int col = c0 + 2 * c;
            float2 v = acc2[r][c];
            v.x = fmaxf(v.x + bs[col], 0.f);
            v.y = fmaxf(v.y + bs[col + 1], 0.f);
            *(__nv_bfloat162*)(out + (size_t)row * 96 + col) = __float22bfloat162_rn(v);
        }
    }
}

// ---------------- layer 2: out_bf16 = relu(agg(in_bf16) @ W + b) ----------------
// block = 64 dst rows, 256 threads. smem: As[96][68] | Ws[96*96] | bs[96]
__global__ void k_layer2(const __nv_bfloat16* __restrict__ in, const float* __restrict__ W,
                         const float* __restrict__ bias, __nv_bfloat16* __restrict__ out) {
    extern __shared__ char sm_raw[];
    float* As = (float*)sm_raw;
    float* Ws = As + 96 * 68;
    float* bs = Ws + 96 * 96;
    int tid = threadIdx.x;
    int row0 = blockIdx.x * 64;

    for (int i = tid; i < 96 * 96 / 4; i += 256)
        *(float4*)&Ws[i * 4] = *(const float4*)&W[i * 4];
    if (tid < 96) bs[tid] = bias[tid];

    // gather over bf16 rows: 4 threads/node, 24 features each (3 x uint4 = 3 x 8 bf16)
    {
        int g = tid >> 2, l = tid & 3;
        int node = row0 + g;
        float dn = g_dinv[node];
        float sc = dn * dn;
        float2 acc[12];
        const uint4* sp = (const uint4*)(in + (size_t)node * 96) + l * 3;
#pragma unroll
        for (int j = 0; j < 3; ++j) {
            uint4 u = sp[j];
            const __nv_bfloat162* h = (const __nv_bfloat162*)&u;
#pragma unroll
            for (int q = 0; q < 4; ++q) {
                float2 v = __bfloat1622float2(h[q]);
                acc[j * 4 + q] = make_float2(v.x * sc, v.y * sc);
            }
        }
        int p1 = g_rowptr[node + 1];
        for (int p = g_rowptr[node]; p < p1; ++p) {
            int s = g_csr[p];
            float nrm = g_dinv[s] * dn;
            const uint4* np = (const uint4*)(in + (size_t)s * 96) + l * 3;
#pragma unroll
            for (int j = 0; j < 3; ++j) {
                uint4 u = np[j];
                const __nv_bfloat162* h = (const __nv_bfloat162*)&u;
#pragma unroll
                for (int q = 0; q < 4; ++q) {
                    float2 v = __bfloat1622float2(h[q]);
                    acc[j * 4 + q].x += v.x * nrm;
                    acc[j * 4 + q].y += v.y * nrm;
                }
            }
        }
#pragma unroll
        for (int j = 0; j < 12; ++j) {
            int f = l * 24 + j * 2;
            As[f * 68 + g] = acc[j].x;
            As[(f + 1) * 68 + g] = acc[j].y;
        }
    }
    __syncthreads();

    // GEMM: [64 x 96] @ [96 x 96]
    int rg = tid & 15, cg = tid >> 4;
    int r0 = rg * 4, c0 = cg * 6;
    float2 acc2[4][3];
#pragma unroll
    for (int r = 0; r < 4; ++r)
#pragma unroll
        for (int c = 0; c < 3; ++c) acc2[r][c] = make_float2(0.f, 0.f);
#pragma unroll 4
    for (int k = 0; k < 96; ++k) {
        float4 av = *(const float4*)&As[k * 68 + r0];
        float2 w0 = *(const float2*)&Ws[k * 96 + c0];
        float2 w1 = *(const float2*)&Ws[k * 96 + c0 + 2];
        float2 w2 = *(const float2*)&Ws[k * 96 + c0 + 4];
        float ar[4] = {av.x, av.y, av.z, av.w};
#pragma unroll
        for (int r = 0; r < 4; ++r) {
            float2 ad = make_float2(ar[r], ar[r]);
            acc2[r][0] = ffma2(ad, w0, acc2[r][0]);
            acc2[r][1] = ffma2(ad, w1, acc2[r][1]);
            acc2[r][2] = ffma2(ad, w2, acc2[r][2]);
        }
    }

    // epilogue: relu + bf16 pack
#pragma unroll
    for (int r = 0; r < 4; ++r) {
        int row = row0 + r0 + r;
#pragma unroll
        for (int c = 0; c < 3; ++c) {
            int col = c0 + 2 * c;
            float2 v = acc2[r][c];
            v.x = fmaxf(v.x + bs[col], 0.f);
            v.y = fmaxf(v.y + bs[col + 1], 0.f);
            *(__nv_bfloat162*)(out + (size_t)row * 96 + col) = __float22bfloat162_rn(v);
        }
    }
}

// ---------------- layer-3 pooled aggregation over bf16: g_psum[b] = sum_{i in b} agg(in)_i ----------------
__global__ void k_pool3(const __nv_bfloat16* __restrict__ in, int side) {
    __shared__ float red[64][96];
    int b = blockIdx.x, tid = threadIdx.x;
    int start = g_boffs[side][b], end = g_boffs[side][b + 1];
    int slot = tid >> 2, l = tid & 3;
    float2 acc[12];
#pragma unroll
    for (int j = 0; j < 12; ++j) acc[j] = make_float2(0.f, 0.f);

    for (int node = start + slot; node < end; node += 64) {
        float dn = g_dinv[node];
        float sc = dn * dn;
        const uint4* sp = (const uint4*)(in + (size_t)node * 96) + l * 3;
#pragma unroll
        for (int j = 0; j < 3; ++j) {
            uint4 u = sp[j];
            const __nv_bfloat162* h = (const __nv_bfloat162*)&u;
#pragma unroll
            for (int q = 0; q < 4; ++q) {
                float2 v = __bfloat1622float2(h[q]);
                acc[j * 4 + q].x += v.x * sc;
                acc[j * 4 + q].y += v.y * sc;
            }
        }
        int p1 = g_rowptr[node + 1];
        for (int p = g_rowptr[node]; p < p1; ++p) {
            int s = g_csr[p];
            float nrm = g_dinv[s] * dn;
            const uint4* np = (const uint4*)(in + (size_t)s * 96) + l * 3;
#pragma unroll
            for (int j = 0; j < 3; ++j) {
                uint4 u = np[j];
                const __nv_bfloat162* h = (const __nv_bfloat162*)&u;
#pragma unroll
                for (int q = 0; q < 4; ++q) {
                    float2 v = __bfloat1622float2(h[q]);
                    acc[j * 4 + q].x += v.x * nrm;
                    acc[j * 4 + q].y += v.y * nrm;
                }
            }
        }
    }
#pragma unroll
    for (int j = 0; j < 12; ++j) {
        int f = l * 24 + j * 2;
        red[slot][f] = acc[j].x;
        red[slot][f + 1] = acc[j].y;
    }
    __syncthreads();
    for (int o = 32; o > 0; o >>= 1) {
        if (slot < o) {
#pragma unroll
            for (int j = 0; j < 6; ++j) {
                float4 a = *(float4*)&red[slot][l * 24 + j * 4];
                float4 c = *(float4*)&red[slot + o][l * 24 + j * 4];
                a.x += c.x; a.y += c.y; a.z += c.z; a.w += c.w;
                *(float4*)&red[slot][l * 24 + j * 4] = a;
            }
        }
        __syncthreads();
    }
    if (slot == 0) {
#pragma unroll
        for (int j = 0; j < 6; ++j)
            *(float4*)&g_psum[side][(size_t)b * 96 + l * 24 + j * 4] =
                *(float4*)&red[0][l * 24 + j * 4];
    }
}

// ---------------- deferred layer-3 GEMM on pooled means: g_mean = (psum/cnt)@W + b ----------------
__global__ void k_small(const float* __restrict__ W, const float* __restrict__ bias, int side) {
    __shared__ float inp[96];
    int b = blockIdx.x, c = threadIdx.x;   // 96 threads
    int cnt = g_boffs[side][b + 1] - g_boffs[side][b];
    float ic = 1.f / fmaxf((float)cnt, 1.f);
    inp[c] = g_psum[side][(size_t)b * 96 + c] * ic;
    __syncthreads();
    float acc = bias[c];
#pragma unroll 4
    for (int k = 0; k < 96; ++k) acc += inp[k] * W[k * 96 + c];
    g_mean[side][(size_t)b * 96 + c] = acc;
}

// ---------------- final MLP: one block per batch row ----------------
__global__ void k_final(const float* __restrict__ W0, const float* __restrict__ b0,
                        const float* __restrict__ W1, const float* __restrict__ b1,
                        float* __restrict__ out) {
    __shared__ float in[320];
    __shared__ float red[128];
    int b = blockIdx.x, t = threadIdx.x;   // 128 threads
    for (int i = t; i < 96; i += 128) {
        in[i]      = g_mean[0][(size_t)b * 96 + i];
        in[96 + i] = g_mean[1][(size_t)b * 96 + i];
    }
    for (int i = t; i < 64; i += 128) {
        in[192 + i] = g_att[0][(size_t)b * 64 + i];
        in[256 + i] = g_att[1][(size_t)b * 64 + i];
    }
    __syncthreads();
    float p = 0.f;
    if (t < 96) {
        float acc = b0[t];
        for (int k = 0; k < 320; ++k) acc += in[k] * W0[(size_t)k * 96 + t];
        p = fmaxf(acc, 0.f) * W1[t];
    }
    red[t] = p;
    __syncthreads();
    for (int s = 64; s > 0; s >>= 1) {
        if (t < s) red[t] += red[t + s];
        __syncthreads();
    }
    if (t == 0) out[b] = red[0] + b1[0];
}

// ---------------- launch ----------------
static inline int TB(int n) { return (n + 255) / 256; }

extern "C" void kernel_launch(void* const* d_in, const int* in_sizes, int n_in,
                              void* d_out, int out_size) {
    const float* x_p   = (const float*)d_in[0];
    const float* x_d   = (const float*)d_in[1];
    // d_in[2], d_in[3]: edge_attr — unused
    const int*   ei_p  = (const int*)d_in[4];
    const int*   ei_d  = (const int*)d_in[5];
    const int*   bat_p = (const int*)d_in[6];
    const int*   bat_d = (const int*)d_in[7];
    const float* gW1 = (const float*)d_in[8];
    const float* gb1 = (const float*)d_in[9];
    const float* gW2 = (const float*)d_in[10];
    const float* gb2 = (const float*)d_in[11];
    const float* convW[2][3] = {
        {(const float*)d_in[12], (const float*)d_in[14], (const float*)d_in[16]},
        {(const float*)d_in[18], (const float*)d_in[20], (const float*)d_in[22]}};
    const float* convB[2][3] = {
        {(const float*)d_in[13], (const float*)d_in[15], (const float*)d_in[17]},
        {(const float*)d_in[19], (const float*)d_in[21], (const float*)d_in[23]}};
    const float* lW0 = (const float*)d_in[24];
    const float* lb0 = (const float*)d_in[25];
    const float* lW1 = (const float*)d_in[26];
    const float* lb1 = (const float*)d_in[27];
    float* out = (float*)d_out;

    __nv_bfloat16 *bufA, *bufB;
    cudaGetSymbolAddress((void**)&bufA, g_bufA);
    cudaGetSymbolAddress((void**)&bufB, g_bufB);

    const int SM_L64  = (64 * 68 + 64 * 96 + 96) * 4;           // 42368
    const int SM_L96  = (96 * 68 + 96 * 96 + 96) * 4;           // 63360
    const int SM_GATE = 64 * 68 * 4 + 64 * 64 * 8 + 2 * 64 * 4; // 50688
    cudaFuncSetAttribute(k_layer1, cudaFuncAttributeMaxDynamicSharedMemorySize, SM_L64);
    cudaFuncSetAttribute(k_layer2, cudaFuncAttributeMaxDynamicSharedMemorySize, SM_L96);
    cudaFuncSetAttribute(k_gate, cudaFuncAttributeMaxDynamicSharedMemorySize, SM_GATE);

    for (int side = 0; side < 2; ++side) {
        const float* x   = side ? x_d : x_p;
        const int*   ei  = side ? ei_d : ei_p;
        const int*   bat = side ? bat_d : bat_p;
        const int* src = ei;
        const int* dst = ei + E_;

        // ---- attention pool (raw x) ----
        k_gate<<<N_ / 64, 256, SM_GATE>>>(x, gW1, gb1, gW2, gb2);
        k_boffs<<<TB(N_), 256>>>(bat, side);
        k_att<<<B_, 256>>>(x, side);

        // ---- CSR build (by dst) + dinv ----
        k_csr_init<<<TB(N_), 256>>>();
        k_count<<<TB(E_), 256>>>(dst);
        k_scan1<<<NTILES_, 1024>>>();
        k_scan2<<<1, 512>>>();
        k_scan3<<<TB(N_), 256>>>();
        k_fill<<<TB(E_), 256>>>(src, dst);
        k_dinv<<<TB(N_), 256>>>();

        // ---- fused agg+GEMM layers 1-2 (bf16 intermediates), pooled layer 3 ----
        k_layer1<<<N_ / 64, 256, SM_L64>>>(x, convW[side][0], convB[side][0], bufA);
        k_layer2<<<N_ / 64, 256, SM_L96>>>(bufA, convW[side][1], convB[side][1], bufB);
        k_pool3<<<B_, 256>>>(bufB, side);
        k_small<<<B_, 96>>>(convW[side][2], convB[side][2], side);
    }

    // ---- final MLP ----
    k_final<<<B_, 128>>>(lW0, lb0, lW1, lb1, out);
}